// round 6
// baseline (speedup 1.0000x reference)
#include <cuda_runtime.h>
#include <stdint.h>

// Problem constants
#define BATCH 16
#define LQ 2048
#define LK 2048
#define DH 64

// Tiling: block = 64 q-rows x full LK, k-tiles of 64. 128 threads (4 warps).
// Warp w owns q rows [w*16, w*16+16). mma.sync m16n8k8 tf32.
#define BQ 64
#define BK 64
#define NT 128
#define NTILES (LK / BK)     // 32
#define KPAD 68              // k smem row stride in floats (conflict-free frag LDS)

#define OUT_ELEMS  ((size_t)BATCH * LQ * DH)   // 2,097,152
#define ATTN_ELEMS ((size_t)BATCH * LQ * LK)   // 67,108,864

// EPS: 2x worst-case tf32 (rna) dot error bound for |q|,|k|~N(0,1), D=64 (+margin)
#define REPAIR_EPS 0.2f

__device__ __forceinline__ float ex2a(float x) {
    float r; asm("ex2.approx.ftz.f32 %0, %1;" : "=f"(r) : "f"(x)); return r;
}
__device__ __forceinline__ unsigned cvt_tf32(float x) {
    unsigned r; asm("cvt.rna.tf32.f32 %0, %1;" : "=r"(r) : "f"(x)); return r;
}
__device__ __forceinline__ void mma_tf32(float c[4],
                                         unsigned a0, unsigned a1, unsigned a2, unsigned a3,
                                         unsigned b0, unsigned b1) {
    asm volatile("mma.sync.aligned.m16n8k8.row.col.f32.tf32.tf32.f32 "
                 "{%0,%1,%2,%3}, {%4,%5,%6,%7}, {%8,%9}, {%0,%1,%2,%3};"
                 : "+f"(c[0]), "+f"(c[1]), "+f"(c[2]), "+f"(c[3])
                 : "r"(a0), "r"(a1), "r"(a2), "r"(a3), "r"(b0), "r"(b1));
}

__global__ __launch_bounds__(NT)
void wta_attn6_kernel(const float* __restrict__ q,
                      const float* __restrict__ k,
                      const float* __restrict__ v,
                      float* __restrict__ out,
                      int write_out, int write_attn, long long attn_off)
{
    __shared__ float ks[BK][KPAD];            // k tile, natural [krow][d], tf32 bit patterns
    __shared__ float tilemax[BQ][NTILES];     // per-(row, tile) tf32 max
    __shared__ float rowsum[BQ];

    const int b    = blockIdx.y;
    const int q0   = blockIdx.x * BQ;
    const int tid  = threadIdx.x;
    const int w    = tid >> 5;
    const int lane = tid & 31;
    const int l4   = lane >> 2;    // groupID (0..7)
    const int lm   = lane & 3;     // threadID_in_group

    const float* qb = q + ((size_t)b * LQ + q0) * DH;
    const float* kb = k + (size_t)b * LK * DH;

    // mma fragment rows for this thread
    const int r0 = w * 16 + l4;
    const int r1 = r0 + 8;

    // ---- A fragments (q): loaded + tf32-converted ONCE, live in regs all kernel ----
    unsigned Af[8][4];
    #pragma unroll
    for (int s = 0; s < 8; s++) {
        Af[s][0] = cvt_tf32(qb[(size_t)r0 * DH + s * 8 + lm]);
        Af[s][1] = cvt_tf32(qb[(size_t)r1 * DH + s * 8 + lm]);
        Af[s][2] = cvt_tf32(qb[(size_t)r0 * DH + s * 8 + lm + 4]);
        Af[s][3] = cvt_tf32(qb[(size_t)r1 * DH + s * 8 + lm + 4]);
    }

    const float C = 0.18033688011112042f;   // 0.125 * log2(e)
    float sum0 = 0.0f, sum1 = 0.0f;

    float4* az = 0;
    if (write_attn)
        az = (float4*)(out + attn_off + ((size_t)b * LQ + q0) * LK);

    for (int t = 0; t < NTILES; t++) {
        __syncthreads();   // previous tile's frag-LDS complete before overwrite

        // ---- load k tile (64 x 64) coalesced, cvt to tf32, natural layout ----
        {
            const float4* src = (const float4*)(kb + (size_t)t * BK * DH);
            #pragma unroll
            for (int i = 0; i < 8; i++) {
                int fi   = tid + i * NT;        // 0..1023
                int krow = fi >> 4;
                int c4   = fi & 15;
                float4 wv = src[fi];
                ks[krow][c4 * 4 + 0] = __uint_as_float(cvt_tf32(wv.x));
                ks[krow][c4 * 4 + 1] = __uint_as_float(cvt_tf32(wv.y));
                ks[krow][c4 * 4 + 2] = __uint_as_float(cvt_tf32(wv.z));
                ks[krow][c4 * 4 + 3] = __uint_as_float(cvt_tf32(wv.w));
            }
        }

        // ---- interleaved zero-fill of this block's attn chunk (64 x 64) ----
        if (write_attn) {
            float4* azc = az + t * (BQ * BK / 4);   // 1024 float4 per tile
            #pragma unroll
            for (int j = 0; j < 8; j++)
                azc[tid + j * NT] = make_float4(0.f, 0.f, 0.f, 0.f);
        }
        __syncthreads();

        // ---- S = Q K^T for this tile: 8 n-chunks x 8 k-slices of mma ----
        float acc[8][4];
        #pragma unroll
        for (int n = 0; n < 8; n++)
            #pragma unroll
            for (int c = 0; c < 4; c++) acc[n][c] = 0.0f;

        #pragma unroll
        for (int n = 0; n < 8; n++) {
            #pragma unroll
            for (int s = 0; s < 8; s++) {
                unsigned b0 = __float_as_uint(ks[n * 8 + l4][s * 8 + lm]);
                unsigned b1 = __float_as_uint(ks[n * 8 + l4][s * 8 + lm + 4]);
                mma_tf32(acc[n], Af[s][0], Af[s][1], Af[s][2], Af[s][3], b0, b1);
            }
        }

        // ---- epilogue: per-row tile max + exp-sum (tf32 scores) ----
        float tm0 = -1e30f, tm1 = -1e30f;
        #pragma unroll
        for (int n = 0; n < 8; n++) {
            tm0 = fmaxf(tm0, fmaxf(acc[n][0], acc[n][1]));
            tm1 = fmaxf(tm1, fmaxf(acc[n][2], acc[n][3]));
            sum0 += ex2a(acc[n][0] * C) + ex2a(acc[n][1] * C);
            sum1 += ex2a(acc[n][2] * C) + ex2a(acc[n][3] * C);
        }
        // reduce across the 4 lanes of each group (cols partitioned by lm)
        #pragma unroll
        for (int off = 1; off <= 2; off <<= 1) {
            tm0 = fmaxf(tm0, __shfl_xor_sync(0xffffffffu, tm0, off));
            tm1 = fmaxf(tm1, __shfl_xor_sync(0xffffffffu, tm1, off));
        }
        if (lm == 0) { tilemax[r0][t] = tm0; tilemax[r1][t] = tm1; }
    }

    // ---- finalize row sums ----
    #pragma unroll
    for (int off = 1; off <= 2; off <<= 1) {
        sum0 += __shfl_xor_sync(0xffffffffu, sum0, off);
        sum1 += __shfl_xor_sync(0xffffffffu, sum1, off);
    }
    if (lm == 0) { rowsum[r0] = sum0; rowsum[r1] = sum1; }
    __syncthreads();

    // ---- repair phase: exact fp32 argmax+max over candidate tiles ----
    // 2 threads per row: tid pair (2r, 2r+1); half picks 32 of 64 k-cols per tile.
    {
        const int r    = tid >> 1;
        const int half = tid & 1;

        // q row in regs (fp32, exact)
        float4 qr[16];
        const float4* qrp = (const float4*)(qb + (size_t)r * DH);
        #pragma unroll
        for (int i = 0; i < 16; i++) qr[i] = qrp[i];

        float best = -1e30f;
        #pragma unroll 8
        for (int t = 0; t < NTILES; t++) best = fmaxf(best, tilemax[r][t]);

        float m = -1e30f;
        int   idx = 0;
        for (int t = 0; t < NTILES; t++) {
            if (tilemax[r][t] < best - REPAIR_EPS) continue;
            const float* ktp = kb + (size_t)t * BK * DH;
            for (int kc = half * 32; kc < half * 32 + 32; kc++) {
                const float4* kr = (const float4*)(ktp + (size_t)kc * DH);
                float p0 = 0.f, p1 = 0.f, p2 = 0.f, p3 = 0.f;
                #pragma unroll
                for (int i = 0; i < 16; i++) {
                    float4 kv = kr[i];
                    float4 qv = qr[i];
                    p0 = fmaf(qv.x, kv.x, p0); p1 = fmaf(qv.y, kv.y, p1);
                    p2 = fmaf(qv.z, kv.z, p2); p3 = fmaf(qv.w, kv.w, p3);
                }
                float s = (p0 + p1) + (p2 + p3);
                if (s > m) { m = s; idx = t * BK + kc; }
            }
        }
        // combine the two halves (half 0 holds lower k indices: tie -> lower idx)
        {
            float om = __shfl_xor_sync(0xffffffffu, m,   1);
            int   oi = __shfl_xor_sync(0xffffffffu, idx, 1);
            if (om > m || (om == m && oi < idx)) { m = om; idx = oi; }
        }

        float p = ex2a(m * C) / rowsum[r];

        if (write_attn && half == 0)
            out[attn_off + ((size_t)b * LQ + q0 + r) * LK + idx] = p;

        if (write_out) {
            const float4* vp = (const float4*)(v + ((size_t)b * LK + idx) * DH + half * 32);
            float4* op = (float4*)(out + ((size_t)b * LQ + q0 + r) * DH + half * 32);
            #pragma unroll
            for (int i = 0; i < 8; i++) {
                float4 vv = vp[i];
                float4 o;
                o.x = p * vv.x; o.y = p * vv.y; o.z = p * vv.z; o.w = p * vv.w;
                op[i] = o;
            }
        }
    }
}

extern "C" void kernel_launch(void* const* d_in, const int* in_sizes, int n_in,
                              void* d_out, int out_size)
{
    const float* q = (const float*)d_in[0];
    const float* k = (const float*)d_in[1];
    const float* v = (const float*)d_in[2];
    float* out = (float*)d_out;

    int wout = 0, wattn = 0;
    long long aoff = 0;
    size_t osz = (size_t)out_size;
    if (osz == OUT_ELEMS + ATTN_ELEMS) { wout = 1; wattn = 1; aoff = (long long)OUT_ELEMS; }
    else if (osz == ATTN_ELEMS)        { wattn = 1; aoff = 0; }
    else                               { wout = 1; }

    dim3 grid(LQ / BQ, BATCH);
    wta_attn6_kernel<<<grid, NT>>>(q, k, v, out, wout, wattn, aoff);
}

// round 7
// speedup vs baseline: 4.1817x; 4.1817x over previous
#include <cuda_runtime.h>
#include <stdint.h>

// Problem constants
#define BATCH 16
#define LQ 2048
#define LK 2048
#define DH 64

// Tiling: block = 64 q-rows x full LK, k-tiles of 64. 128 threads (4 warps).
// Warp w owns q rows [w*16, w*16+16) in the mma mainloop.
#define BQ 64
#define BK 64
#define NT 128
#define NTILES (LK / BK)     // 32
#define KPAD 68              // k smem row stride (conflict-free frag LDS)

#define OUT_ELEMS  ((size_t)BATCH * LQ * DH)   // 2,097,152
#define ATTN_ELEMS ((size_t)BATCH * LQ * LK)   // 67,108,864

// 2x worst-case tf32(rna) dot-error bound for this data (err <~ 0.04) + margin
#define REPAIR_EPS 0.2f

__device__ __forceinline__ float ex2a(float x) {
    float r; asm("ex2.approx.ftz.f32 %0, %1;" : "=f"(r) : "f"(x)); return r;
}
__device__ __forceinline__ unsigned cvt_tf32(float x) {
    unsigned r; asm("cvt.rna.tf32.f32 %0, %1;" : "=r"(r) : "f"(x)); return r;
}
__device__ __forceinline__ void mma_tf32(float c[4],
                                         unsigned a0, unsigned a1, unsigned a2, unsigned a3,
                                         unsigned b0, unsigned b1) {
    asm volatile("mma.sync.aligned.m16n8k8.row.col.f32.tf32.tf32.f32 "
                 "{%0,%1,%2,%3}, {%4,%5,%6,%7}, {%8,%9}, {%0,%1,%2,%3};"
                 : "+f"(c[0]), "+f"(c[1]), "+f"(c[2]), "+f"(c[3])
                 : "r"(a0), "r"(a1), "r"(a2), "r"(a3), "r"(b0), "r"(b1));
}

__global__ __launch_bounds__(NT)
void wta_attn7_kernel(const float* __restrict__ q,
                      const float* __restrict__ k,
                      const float* __restrict__ v,
                      float* __restrict__ out,
                      int write_out, int write_attn, long long attn_off)
{
    __shared__ float ks[BK][KPAD];                 // 17.4 KB  tf32 k tile
    __shared__ float tilemax[BQ][NTILES];          //  8  KB
    __shared__ float rowsum[BQ];
    __shared__ int   wl[BQ * NTILES];              //  8  KB  worklist (hard upper bound)
    __shared__ unsigned long long res[BQ];         // packed (key(score) << 32) | (~idx)
    __shared__ float pval[BQ];
    __shared__ int   widx[BQ];
    __shared__ int   wlcnt;

    const int b    = blockIdx.y;
    const int q0   = blockIdx.x * BQ;
    const int tid  = threadIdx.x;
    const int w    = tid >> 5;
    const int lane = tid & 31;
    const int l4   = lane >> 2;    // groupID (0..7)
    const int lm   = lane & 3;     // thread-in-group

    const float* qb = q + ((size_t)b * LQ + q0) * DH;
    const float* kb = k + (size_t)b * LK * DH;

    // mma fragment rows for this thread
    const int r0 = w * 16 + l4;
    const int r1 = r0 + 8;

    // ---- A fragments (q): tf32-converted once, resident in regs ----
    unsigned Af[8][4];
    #pragma unroll
    for (int s = 0; s < 8; s++) {
        Af[s][0] = cvt_tf32(qb[(size_t)r0 * DH + s * 8 + lm]);
        Af[s][1] = cvt_tf32(qb[(size_t)r1 * DH + s * 8 + lm]);
        Af[s][2] = cvt_tf32(qb[(size_t)r0 * DH + s * 8 + lm + 4]);
        Af[s][3] = cvt_tf32(qb[(size_t)r1 * DH + s * 8 + lm + 4]);
    }

    const float C = 0.18033688011112042f;   // 0.125 * log2(e)
    float sum0 = 0.0f, sum1 = 0.0f;

    float4* az = 0;
    if (write_attn)
        az = (float4*)(out + attn_off + ((size_t)b * LQ + q0) * LK);

    // ================= mainloop: tf32 QK^T + tilemax + exp-sum =================
    for (int t = 0; t < NTILES; t++) {
        __syncthreads();

        // k tile (64 x 64) coalesced load, cvt to tf32, natural layout
        {
            const float4* src = (const float4*)(kb + (size_t)t * BK * DH);
            #pragma unroll
            for (int i = 0; i < 8; i++) {
                int fi   = tid + i * NT;
                int krow = fi >> 4;
                int c4   = fi & 15;
                float4 wv = src[fi];
                ks[krow][c4 * 4 + 0] = __uint_as_float(cvt_tf32(wv.x));
                ks[krow][c4 * 4 + 1] = __uint_as_float(cvt_tf32(wv.y));
                ks[krow][c4 * 4 + 2] = __uint_as_float(cvt_tf32(wv.z));
                ks[krow][c4 * 4 + 3] = __uint_as_float(cvt_tf32(wv.w));
            }
        }

        // interleaved zero-fill of this block's attn chunk
        if (write_attn) {
            float4* azc = az + t * (BQ * BK / 4);
            #pragma unroll
            for (int j = 0; j < 8; j++)
                azc[tid + j * NT] = make_float4(0.f, 0.f, 0.f, 0.f);
        }
        __syncthreads();

        float acc[8][4];
        #pragma unroll
        for (int n = 0; n < 8; n++)
            #pragma unroll
            for (int c = 0; c < 4; c++) acc[n][c] = 0.0f;

        #pragma unroll
        for (int n = 0; n < 8; n++) {
            #pragma unroll
            for (int s = 0; s < 8; s++) {
                unsigned b0 = __float_as_uint(ks[n * 8 + l4][s * 8 + lm]);
                unsigned b1 = __float_as_uint(ks[n * 8 + l4][s * 8 + lm + 4]);
                mma_tf32(acc[n], Af[s][0], Af[s][1], Af[s][2], Af[s][3], b0, b1);
            }
        }

        float tm0 = -1e30f, tm1 = -1e30f;
        #pragma unroll
        for (int n = 0; n < 8; n++) {
            tm0 = fmaxf(tm0, fmaxf(acc[n][0], acc[n][1]));
            tm1 = fmaxf(tm1, fmaxf(acc[n][2], acc[n][3]));
            sum0 += ex2a(acc[n][0] * C) + ex2a(acc[n][1] * C);
            sum1 += ex2a(acc[n][2] * C) + ex2a(acc[n][3] * C);
        }
        #pragma unroll
        for (int off = 1; off <= 2; off <<= 1) {
            tm0 = fmaxf(tm0, __shfl_xor_sync(0xffffffffu, tm0, off));
            tm1 = fmaxf(tm1, __shfl_xor_sync(0xffffffffu, tm1, off));
        }
        if (lm == 0) { tilemax[r0][t] = tm0; tilemax[r1][t] = tm1; }
    }

    // row sums
    #pragma unroll
    for (int off = 1; off <= 2; off <<= 1) {
        sum0 += __shfl_xor_sync(0xffffffffu, sum0, off);
        sum1 += __shfl_xor_sync(0xffffffffu, sum1, off);
    }
    if (lm == 0) { rowsum[r0] = sum0; rowsum[r1] = sum1; }

    if (tid == 0) wlcnt = 0;
    if (tid < BQ) res[tid] = 0ull;
    __syncthreads();

    // ================= build candidate worklist (uniform, bounded) =================
    if (tid < BQ) {
        const int r = tid;
        float best = -1e30f;
        #pragma unroll 8
        for (int t = 0; t < NTILES; t++) best = fmaxf(best, tilemax[r][t]);
        const float thr = best - REPAIR_EPS;
        for (int t = 0; t < NTILES; t++) {
            if (tilemax[r][t] >= thr) {
                int p = atomicAdd(&wlcnt, 1);
                wl[p] = (r << 5) | t;           // r*32 + t, always < 2048
            }
        }
    }
    __syncthreads();
    const int cnt = wlcnt;

    // ================= warp-cooperative exact repair =================
    // One warp per item. Lanes 0-15 handle even cols, 16-31 odd cols; the 16
    // lanes of a half each cover one float4 chunk of the 64-dim dot (coalesced).
    for (int it = w; it < cnt; it += NT / 32) {
        const int e = wl[it];
        const int r = e >> 5;
        const int t = e & 31;

        const float4 qv = *(const float4*)(qb + (size_t)r * DH + (lane & 15) * 4);
        const float* kt = kb + (size_t)t * BK * DH;

        float bm = -1e30f;
        int   bi = 0;
        #pragma unroll 4
        for (int rr = 0; rr < 32; rr++) {
            const int col = rr * 2 + (lane >> 4);
            const float4 kv = *(const float4*)(kt + (size_t)col * DH + (lane & 15) * 4);
            float p = fmaf(qv.x, kv.x, fmaf(qv.y, kv.y,
                      fmaf(qv.z, kv.z, qv.w * kv.w)));
            p += __shfl_xor_sync(0xffffffffu, p, 8, 16);
            p += __shfl_xor_sync(0xffffffffu, p, 4, 16);
            p += __shfl_xor_sync(0xffffffffu, p, 2, 16);
            p += __shfl_xor_sync(0xffffffffu, p, 1, 16);
            // every lane of the half now holds the full dot for its col
            if (p > bm) { bm = p; bi = col; }   // lowest col wins ties
        }
        // merge even-col half with odd-col half
        {
            float om = __shfl_xor_sync(0xffffffffu, bm, 16);
            int   oi = __shfl_xor_sync(0xffffffffu, bi, 16);
            if (om > bm || (om == bm && oi < bi)) { bm = om; bi = oi; }
        }
        if (lane == 0) {
            unsigned u = __float_as_uint(bm);
            u = (u & 0x80000000u) ? ~u : (u | 0x80000000u);     // sortable key
            unsigned long long pk =
                ((unsigned long long)u << 32) |
                (unsigned)(0xFFFFFFFFu - (unsigned)(t * BK + bi)); // tie -> lower idx
            atomicMax(&res[r], pk);
        }
    }
    __syncthreads();

    // ================= finalize: p = exp(m)/sum, scatter + dense out =================
    if (tid < BQ) {
        const unsigned long long pk = res[tid];
        unsigned u = (unsigned)(pk >> 32);
        unsigned bits = (u & 0x80000000u) ? (u & 0x7FFFFFFFu) : ~u;
        float m = __uint_as_float(bits);
        int idx = (int)(0xFFFFFFFFu - (unsigned)(pk & 0xFFFFFFFFu));
        float p = ex2a(m * C) / rowsum[tid];
        pval[tid] = p;
        widx[tid] = idx;
        if (write_attn)
            out[attn_off + ((size_t)b * LQ + q0 + tid) * LK + idx] = p;
    }
    __syncthreads();

    if (write_out) {
        #pragma unroll
        for (int i = tid; i < BQ * (DH / 4); i += NT) {
            const int r = i >> 4;
            const int c = i & 15;
            const float p = pval[r];
            const float4 vv = *(const float4*)(v + ((size_t)b * LK + widx[r]) * DH + c * 4);
            float4 o;
            o.x = p * vv.x; o.y = p * vv.y; o.z = p * vv.z; o.w = p * vv.w;
            *(float4*)(out + ((size_t)b * LQ + q0 + r) * DH + c * 4) = o;
        }
    }
}

extern "C" void kernel_launch(void* const* d_in, const int* in_sizes, int n_in,
                              void* d_out, int out_size)
{
    const float* q = (const float*)d_in[0];
    const float* k = (const float*)d_in[1];
    const float* v = (const float*)d_in[2];
    float* out = (float*)d_out;

    int wout = 0, wattn = 0;
    long long aoff = 0;
    size_t osz = (size_t)out_size;
    if (osz == OUT_ELEMS + ATTN_ELEMS) { wout = 1; wattn = 1; aoff = (long long)OUT_ELEMS; }
    else if (osz == ATTN_ELEMS)        { wattn = 1; aoff = 0; }
    else                               { wout = 1; }

    dim3 grid(LQ / BQ, BATCH);
    wta_attn7_kernel<<<grid, NT>>>(q, k, v, out, wout, wattn, aoff);
}

// round 8
// speedup vs baseline: 4.3860x; 1.0488x over previous
#include <cuda_runtime.h>
#include <stdint.h>

// Problem constants
#define BATCH 16
#define LQ 2048
#define LK 2048
#define DH 64

// Block = 64 q-rows x full LK. 256 threads (8 warps).
// Warp w: row-group wg = w&3 (rows wg*16..+16), k-half = w>>2 (tiles half*16..+16).
#define BQ 64
#define BK 64
#define NT 256
#define NTILES (LK / BK)     // 32
#define HTILES (NTILES / 2)  // 16 per warp-group
#define KPAD 68

#define OUT_ELEMS  ((size_t)BATCH * LQ * DH)   // 2,097,152
#define ATTN_ELEMS ((size_t)BATCH * LQ * LK)   // 67,108,864

#define REPAIR_EPS 0.2f

__device__ __forceinline__ float ex2a(float x) {
    float r; asm("ex2.approx.ftz.f32 %0, %1;" : "=f"(r) : "f"(x)); return r;
}
__device__ __forceinline__ unsigned cvt_tf32(float x) {
    unsigned r; asm("cvt.rna.tf32.f32 %0, %1;" : "=r"(r) : "f"(x)); return r;
}
__device__ __forceinline__ void mma_tf32(float c[4],
                                         unsigned a0, unsigned a1, unsigned a2, unsigned a3,
                                         unsigned b0, unsigned b1) {
    asm volatile("mma.sync.aligned.m16n8k8.row.col.f32.tf32.tf32.f32 "
                 "{%0,%1,%2,%3}, {%4,%5,%6,%7}, {%8,%9}, {%0,%1,%2,%3};"
                 : "+f"(c[0]), "+f"(c[1]), "+f"(c[2]), "+f"(c[3])
                 : "r"(a0), "r"(a1), "r"(a2), "r"(a3), "r"(b0), "r"(b1));
}

__global__ __launch_bounds__(NT)
void wta_attn8_kernel(const float* __restrict__ q,
                      const float* __restrict__ k,
                      const float* __restrict__ v,
                      float* __restrict__ out,
                      int write_out, int write_attn, long long attn_off)
{
    __shared__ float ks[2][BK][KPAD];          // 34.8 KB: two resident tf32 k tiles
    __shared__ float tilemax[BQ][NTILES];      //  8  KB
    __shared__ float rs[2][BQ];                // per-half partial row sums
    __shared__ float rowsum[BQ];
    __shared__ float pval[BQ];
    __shared__ int   widx[BQ];

    const int b    = blockIdx.y;
    const int q0   = blockIdx.x * BQ;
    const int tid  = threadIdx.x;
    const int w    = tid >> 5;
    const int lane = tid & 31;
    const int wg   = w & 3;        // row group
    const int half = w >> 2;       // k half
    const int l4   = lane >> 2;
    const int lm   = lane & 3;

    const float* qb = q + ((size_t)b * LQ + q0) * DH;
    const float* kb = k + (size_t)b * LK * DH;

    const int r0 = wg * 16 + l4;
    const int r1 = r0 + 8;

    // ---- A fragments (q): tf32 once, resident in regs ----
    unsigned Af[8][4];
    #pragma unroll
    for (int s = 0; s < 8; s++) {
        Af[s][0] = cvt_tf32(qb[(size_t)r0 * DH + s * 8 + lm]);
        Af[s][1] = cvt_tf32(qb[(size_t)r1 * DH + s * 8 + lm]);
        Af[s][2] = cvt_tf32(qb[(size_t)r0 * DH + s * 8 + lm + 4]);
        Af[s][3] = cvt_tf32(qb[(size_t)r1 * DH + s * 8 + lm + 4]);
    }

    const float C = 0.18033688011112042f;   // 0.125 * log2(e)
    float sum0 = 0.0f, sum1 = 0.0f;

    float4* az = 0;
    if (write_attn)
        az = (float4*)(out + attn_off + ((size_t)b * LQ + q0) * LK);

    // ================= mainloop: 16 iterations, 2 tiles resident =================
    for (int it = 0; it < HTILES; it++) {
        __syncthreads();

        // load tile it -> buf0, tile it+16 -> buf1 (coalesced, cvt tf32)
        #pragma unroll
        for (int i = 0; i < 8; i++) {
            int fi   = tid + i * NT;       // 0..2047
            int buf  = fi >> 10;
            int wi   = fi & 1023;
            int krow = wi >> 4;
            int c4   = wi & 15;
            const float4* src = (const float4*)(kb + (size_t)(it + buf * HTILES) * BK * DH);
            float4 wv = src[wi];
            ks[buf][krow][c4 * 4 + 0] = __uint_as_float(cvt_tf32(wv.x));
            ks[buf][krow][c4 * 4 + 1] = __uint_as_float(cvt_tf32(wv.y));
            ks[buf][krow][c4 * 4 + 2] = __uint_as_float(cvt_tf32(wv.z));
            ks[buf][krow][c4 * 4 + 3] = __uint_as_float(cvt_tf32(wv.w));
        }

        // interleaved zero-fill: chunks for tiles it and it+16
        if (write_attn) {
            #pragma unroll
            for (int j = 0; j < 8; j++) {
                int fi  = tid + j * NT;
                int buf = fi >> 10;
                int wi  = fi & 1023;
                az[(size_t)(it + buf * HTILES) * (BQ * BK / 4) + wi] =
                    make_float4(0.f, 0.f, 0.f, 0.f);
            }
        }
        __syncthreads();

        const int t = it + half * HTILES;

        float acc[8][4];
        #pragma unroll
        for (int n = 0; n < 8; n++)
            #pragma unroll
            for (int c = 0; c < 4; c++) acc[n][c] = 0.0f;

        #pragma unroll
        for (int n = 0; n < 8; n++) {
            #pragma unroll
            for (int s = 0; s < 8; s++) {
                unsigned b0 = __float_as_uint(ks[half][n * 8 + l4][s * 8 + lm]);
                unsigned b1 = __float_as_uint(ks[half][n * 8 + l4][s * 8 + lm + 4]);
                mma_tf32(acc[n], Af[s][0], Af[s][1], Af[s][2], Af[s][3], b0, b1);
            }
        }

        float tm0 = -1e30f, tm1 = -1e30f;
        #pragma unroll
        for (int n = 0; n < 8; n++) {
            tm0 = fmaxf(tm0, fmaxf(acc[n][0], acc[n][1]));
            tm1 = fmaxf(tm1, fmaxf(acc[n][2], acc[n][3]));
            sum0 += ex2a(acc[n][0] * C) + ex2a(acc[n][1] * C);
            sum1 += ex2a(acc[n][2] * C) + ex2a(acc[n][3] * C);
        }
        #pragma unroll
        for (int off = 1; off <= 2; off <<= 1) {
            tm0 = fmaxf(tm0, __shfl_xor_sync(0xffffffffu, tm0, off));
            tm1 = fmaxf(tm1, __shfl_xor_sync(0xffffffffu, tm1, off));
        }
        if (lm == 0) { tilemax[r0][t] = tm0; tilemax[r1][t] = tm1; }
    }

    // partial row sums per half
    #pragma unroll
    for (int off = 1; off <= 2; off <<= 1) {
        sum0 += __shfl_xor_sync(0xffffffffu, sum0, off);
        sum1 += __shfl_xor_sync(0xffffffffu, sum1, off);
    }
    if (lm == 0) { rs[half][r0] = sum0; rs[half][r1] = sum1; }
    __syncthreads();

    if (tid < BQ) rowsum[tid] = rs[0][tid] + rs[1][tid];
    __syncthreads();

    // ================= repair: one warp per row, warp-uniform branches =================
    #pragma unroll 1
    for (int rr8 = 0; rr8 < BQ / 8; rr8++) {
        const int r = w * 8 + rr8;

        const float tmv = tilemax[r][lane];      // 32 lanes = 32 tiles
        float best = tmv;
        #pragma unroll
        for (int off = 16; off > 0; off >>= 1)
            best = fmaxf(best, __shfl_xor_sync(0xffffffffu, best, off));
        const float thr = best - REPAIR_EPS;

        const float4 qv = *(const float4*)(qb + (size_t)r * DH + (lane & 15) * 4);

        float bm = -1e30f;
        int   bi = 0;
        #pragma unroll 1
        for (int t = 0; t < NTILES; t++) {
            if (__shfl_sync(0xffffffffu, tmv, t) < thr) continue;   // warp-uniform
            const float* kt = kb + (size_t)t * BK * DH;
            #pragma unroll 4
            for (int rr = 0; rr < 32; rr++) {
                const int col = rr * 2 + (lane >> 4);
                const float4 kv = *(const float4*)(kt + (size_t)col * DH + (lane & 15) * 4);
                float p = fmaf(qv.x, kv.x, fmaf(qv.y, kv.y,
                          fmaf(qv.z, kv.z, qv.w * kv.w)));
                p += __shfl_xor_sync(0xffffffffu, p, 8, 16);
                p += __shfl_xor_sync(0xffffffffu, p, 4, 16);
                p += __shfl_xor_sync(0xffffffffu, p, 2, 16);
                p += __shfl_xor_sync(0xffffffffu, p, 1, 16);
                if (p > bm) { bm = p; bi = t * BK + col; }  // strict > : lowest t/col kept
            }
        }
        // final reduce across all 32 lanes (tie -> lower idx)
        #pragma unroll
        for (int off = 16; off > 0; off >>= 1) {
            float om = __shfl_xor_sync(0xffffffffu, bm, off);
            int   oi = __shfl_xor_sync(0xffffffffu, bi, off);
            if (om > bm || (om == bm && oi < bi)) { bm = om; bi = oi; }
        }
        if (lane == 0) {
            float p = ex2a(bm * C) / rowsum[r];
            pval[r] = p;
            widx[r] = bi;
            if (write_attn)
                out[attn_off + ((size_t)b * LQ + q0 + r) * LK + bi] = p;
        }
    }
    __syncthreads();

    // ================= dense output =================
    if (write_out) {
        #pragma unroll
        for (int i = tid; i < BQ * (DH / 4); i += NT) {
            const int r = i >> 4;
            const int c = i & 15;
            const float p = pval[r];
            const float4 vv = *(const float4*)(v + ((size_t)b * LK + widx[r]) * DH + c * 4);
            float4 o;
            o.x = p * vv.x; o.y = p * vv.y; o.z = p * vv.z; o.w = p * vv.w;
            *(float4*)(out + ((size_t)b * LQ + q0 + r) * DH + c * 4) = o;
        }
    }
}

extern "C" void kernel_launch(void* const* d_in, const int* in_sizes, int n_in,
                              void* d_out, int out_size)
{
    const float* q = (const float*)d_in[0];
    const float* k = (const float*)d_in[1];
    const float* v = (const float*)d_in[2];
    float* out = (float*)d_out;

    int wout = 0, wattn = 0;
    long long aoff = 0;
    size_t osz = (size_t)out_size;
    if (osz == OUT_ELEMS + ATTN_ELEMS) { wout = 1; wattn = 1; aoff = (long long)OUT_ELEMS; }
    else if (osz == ATTN_ELEMS)        { wattn = 1; aoff = 0; }
    else                               { wout = 1; }

    dim3 grid(LQ / BQ, BATCH);
    wta_attn8_kernel<<<grid, NT>>>(q, k, v, out, wout, wattn, aoff);
}